// round 3
// baseline (speedup 1.0000x reference)
#include <cuda_runtime.h>

// GMM score, d=1. out[j] = (evals[j] - x[j]) / sigma2[j]
//   sigma2[j] = (exp(2*t*ln 25) - 1) / (2*ln 25)
//   pdf[i][j] = exp(-0.5*(tr[i]-x[j])^2 / sigma2[j])
//   evals[j]  = sum_i pdf*tr / sum_i pdf   (0 if denominator == 0)
//
// R2: 8-way N-split inside each CTA to get 8 warps/SMSP (was 1).
// TPB=1024: lane q = tid%128 selects the query, group g = tid/128 selects a
// 1/8 chunk of the train points. Partial (num,den) reduced via shared.
// Inner loop per element: LDS.64 (broadcast) + 2 FFMA (exponent poly in base-2)
// + ex2.approx (MUFU) + FFMA (num) + FADD (den)
//   -> FMA pipe 4 ops x rt2 = 8 cyc/warp-iter, MUFU 1 x rt8 = 8 cyc. Both bind.

#define TPB     1024
#define QPB     128          // queries per CTA
#define SPLIT   (TPB / QPB)  // 8-way split of the N loop

__global__ __launch_bounds__(TPB, 1)
void gmm_score_kernel(const float* __restrict__ x,
                      const float* __restrict__ t,
                      const float* __restrict__ train,
                      float* __restrict__ out,
                      int B, int N)
{
    extern __shared__ float2 s_tr[];                 // N x {tr, tr^2}
    __shared__ float s_num[SPLIT][QPB];
    __shared__ float s_den[SPLIT][QPB];

    // Stage train points once per CTA
    for (int i = threadIdx.x; i < N; i += TPB) {
        float v = train[i];
        s_tr[i] = make_float2(v, v * v);
    }

    const int q  = threadIdx.x & (QPB - 1);          // query lane 0..127
    const int g  = threadIdx.x / QPB;                // N-chunk group 0..7
    const int j  = blockIdx.x * QPB + q;             // global query id

    // All threads in a warp share g => uniform bounds, no divergence.
    float xv = 0.0f, tv = 0.5f;
    if (j < B) { xv = x[j]; tv = t[j]; }

    const float LOG_S   = 3.2188758248682006f;       // ln(25)
    const float INV_LN2 = 1.4426950408889634f;
    float sigma2 = (expf(2.0f * tv * LOG_S) - 1.0f) / (2.0f * LOG_S);

    // k = -0.5/(sigma2*ln2) so exp(-0.5 d^2/sigma2) = 2^(k*d^2)
    const float k  = -0.5f * INV_LN2 / sigma2;
    const float c1 = -2.0f * k * xv;                 // coeff of tr
    const float c0 = k * xv * xv;                    // constant

    const int chunk = N / SPLIT;
    const int i0 = g * chunk;
    const int i1 = (g == SPLIT - 1) ? N : i0 + chunk;

    float num = 0.0f;
    float den = 0.0f;

    __syncthreads();                                 // train staged

    #pragma unroll 16
    for (int i = i0; i < i1; ++i) {
        float2 v = s_tr[i];                          // broadcast LDS.64
        float a = fmaf(k, v.y, fmaf(c1, v.x, c0));   // k*tr^2 + c1*tr + c0
        float e;
        asm("ex2.approx.ftz.f32 %0, %1;" : "=f"(e) : "f"(a));
        num = fmaf(e, v.x, num);
        den += e;
    }

    s_num[g][q] = num;
    s_den[g][q] = den;
    __syncthreads();

    // First 128 threads reduce the 8 partials and run the epilogue.
    if (threadIdx.x < QPB && j < B) {
        float tn = 0.0f, td = 0.0f;
        #pragma unroll
        for (int s = 0; s < SPLIT; ++s) {
            tn += s_num[s][threadIdx.x];
            td += s_den[s][threadIdx.x];
        }
        float evals = (td == 0.0f) ? 0.0f : (tn / td);
        out[j] = (evals - xv) / sigma2;
    }
}

extern "C" void kernel_launch(void* const* d_in, const int* in_sizes, int n_in,
                              void* d_out, int out_size)
{
    const float* x     = (const float*)d_in[0];
    const float* t     = (const float*)d_in[1];
    const float* train = (const float*)d_in[2];
    float* out = (float*)d_out;

    int B = in_sizes[0];   // 16384 queries
    int N = in_sizes[2];   // 16384 train points

    size_t smem = (size_t)N * sizeof(float2);        // 128 KB dynamic

    static int attr_done = 0;
    if (!attr_done) {
        cudaFuncSetAttribute(gmm_score_kernel,
                             cudaFuncAttributeMaxDynamicSharedMemorySize,
                             (int)smem);
        attr_done = 1;
    }

    int grid = (B + QPB - 1) / QPB;                  // 128 CTAs
    gmm_score_kernel<<<grid, TPB, smem>>>(x, t, train, out, B, N);
}

// round 4
// speedup vs baseline: 1.7550x; 1.7550x over previous
#include <cuda_runtime.h>

// GMM score, d=1, two-phase.
//   sigma2(t) = (exp(2 t ln25) - 1) / (2 ln25)
//   out[j] = (evals[j] - x[j]) / sigma2[j],  evals = sum_i e_ij tr_i / sum_i e_ij
//   e_ij = exp(-0.5 (tr_i - x_j)^2 / sigma2_j) = 2^( (k*tr + c1)*tr + c0 )
//   k = -inv(2 ln2 sigma2), c1 = -2 k x, c0 = k x^2   (Horner, 2 FFMA2 per pair)
//
// Phase A: units of (32 queries x 512 train elems), 16384 units statically
// interleaved over all SMs (grid = SM count, 8 warps/CTA = 2/SMSP).
// Inner loop per 2 query-elements: LDS.64 + 2 FFMA2 + 2 MUFU + FFMA2 + FADD2.
// MUFU binds at 8 cyc/qe -> ~113k cyc over 148+ SMs.
// Phase B: reduce 32 partials per query + epilogue.

#define TPB_A   256
#define WPB     (TPB_A / 32)
#define CHUNKS  32
#define MAXB    16384

__device__ float2 g_part[CHUNKS * MAXB];   // (num, den) partials

#define PACK2(d, lo, hi) \
    asm("mov.b64 %0, {%1, %2};" : "=l"(d) : "f"(lo), "f"(hi))
#define UNPACK2(lo, hi, s) \
    asm("mov.b64 {%0, %1}, %2;" : "=f"(lo), "=f"(hi) : "l"(s))
#define FMA2(d, a, b, c) \
    asm("fma.rn.f32x2 %0, %1, %2, %3;" : "=l"(d) : "l"(a), "l"(b), "l"(c))
#define ADD2(d, a, b) \
    asm("add.rn.f32x2 %0, %1, %2;" : "=l"(d) : "l"(a), "l"(b))
#define EX2(d, a) \
    asm("ex2.approx.ftz.f32 %0, %1;" : "=f"(d) : "f"(a))

__device__ __forceinline__ float sigma2_of(float tv) {
    const float LOG_S = 3.2188758248682006f;   // ln 25
    return (expf(2.0f * tv * LOG_S) - 1.0f) / (2.0f * LOG_S);
}

__global__ __launch_bounds__(TPB_A, 1)
void gmm_partial_kernel(const float* __restrict__ x,
                        const float* __restrict__ t,
                        const float* __restrict__ train,
                        int B, int N, int PL /* pairs per chunk */)
{
    extern __shared__ float2 sp[];   // CHUNKS*PL train pairs (padded)

    // Stage train points as pairs; pad with -1e30 => exp arg -> -inf => e = 0,
    // and 0 * (-1e30) = -0 in the num accumulator (no NaN).
    const int tot = CHUNKS * PL;
    for (int i = threadIdx.x; i < tot; i += TPB_A) {
        int e0 = 2 * i, e1 = 2 * i + 1;
        float a = (e0 < N) ? train[e0] : -1e30f;
        float b = (e1 < N) ? train[e1] : -1e30f;
        sp[i] = make_float2(a, b);
    }
    __syncthreads();

    const int lane   = threadIdx.x & 31;
    const int wid    = threadIdx.x >> 5;
    const int wgid   = blockIdx.x * WPB + wid;
    const int nwarps = gridDim.x * WPB;

    const int qwarps = (B + 31) >> 5;
    const int units  = qwarps * CHUNKS;

    const float INV_LN2 = 1.4426950408889634f;

    for (int u = wgid; u < units; u += nwarps) {
        const int qw = u >> 5;          // CHUNKS == 32
        const int c  = u & (CHUNKS - 1);
        const int q  = qw * 32 + lane;
        const bool act = (q < B);

        float xv = 0.0f, tv = 0.5f;
        if (act) { xv = x[q]; tv = t[q]; }

        const float sigma2 = sigma2_of(tv);
        const float k  = -0.5f * INV_LN2 / sigma2;
        const float c1 = -2.0f * k * xv;
        const float c0 = k * xv * xv;

        unsigned long long KK, C1, C0, num2, den2;
        PACK2(KK, k, k);
        PACK2(C1, c1, c1);
        PACK2(C0, c0, c0);
        num2 = 0ULL; den2 = 0ULL;      // (0.0f, 0.0f)

        const float2* __restrict__ p = sp + c * PL;

        #pragma unroll 8
        for (int i = 0; i < PL; ++i) {
            float2 v = p[i];                       // LDS.64 broadcast
            unsigned long long P, t1, a2, E;
            PACK2(P, v.x, v.y);                    // aligned pair: should vanish
            FMA2(t1, KK, P, C1);                   // k*tr + c1
            FMA2(a2, t1, P, C0);                   // (k*tr + c1)*tr + c0
            float al, ah, e0, e1;
            UNPACK2(al, ah, a2);
            EX2(e0, al);
            EX2(e1, ah);
            PACK2(E, e0, e1);
            FMA2(num2, E, P, num2);
            ADD2(den2, den2, E);
        }

        float nlo, nhi, dlo, dhi;
        UNPACK2(nlo, nhi, num2);
        UNPACK2(dlo, dhi, den2);
        if (act)
            g_part[c * MAXB + q] = make_float2(nlo + nhi, dlo + dhi);
    }
}

__global__ void gmm_final_kernel(const float* __restrict__ x,
                                 const float* __restrict__ t,
                                 float* __restrict__ out,
                                 int B)
{
    int j = blockIdx.x * blockDim.x + threadIdx.x;
    if (j >= B) return;

    float num = 0.0f, den = 0.0f;
    #pragma unroll
    for (int c = 0; c < CHUNKS; ++c) {
        float2 pd = g_part[c * MAXB + j];
        num += pd.x;
        den += pd.y;
    }
    float xv = x[j];
    float sigma2 = sigma2_of(t[j]);
    float evals = (den == 0.0f) ? 0.0f : (num / den);
    out[j] = (evals - xv) / sigma2;
}

extern "C" void kernel_launch(void* const* d_in, const int* in_sizes, int n_in,
                              void* d_out, int out_size)
{
    const float* x     = (const float*)d_in[0];
    const float* t     = (const float*)d_in[1];
    const float* train = (const float*)d_in[2];
    float* out = (float*)d_out;

    int B = in_sizes[0];   // 16384
    int N = in_sizes[2];   // 16384

    int npairs = (N + 1) / 2;
    int PL = (npairs + CHUNKS - 1) / CHUNKS;          // 256 for N=16384
    size_t smem = (size_t)CHUNKS * PL * sizeof(float2);  // 64 KB

    static int sms = 0;
    if (!sms) {
        cudaDeviceGetAttribute(&sms, cudaDevAttrMultiProcessorCount, 0);
        if (sms <= 0) sms = 148;
        cudaFuncSetAttribute(gmm_partial_kernel,
                             cudaFuncAttributeMaxDynamicSharedMemorySize,
                             (int)smem);
    }

    gmm_partial_kernel<<<sms, TPB_A, smem>>>(x, t, train, B, N, PL);
    gmm_final_kernel<<<(B + 255) / 256, 256>>>(x, t, out, B);
}